// round 2
// baseline (speedup 1.0000x reference)
#include <cuda_runtime.h>
#include <math.h>

#define B_ 2
#define S_ 2048
#define E_ 1024
#define H_ 16
#define D_ 64
#define M_ (B_*S_)   // 4096 rows

// Scratch (allocation-free): q/k/v in [B,H,S,D] layout, attn in [B,S,E]
__device__ float g_q[(size_t)B_*H_*S_*D_];
__device__ float g_k[(size_t)B_*H_*S_*D_];
__device__ float g_v[(size_t)B_*H_*S_*D_];
__device__ float g_attn[(size_t)B_*S_*E_];

// ---------------------------------------------------------------------------
// tf32 helpers
// ---------------------------------------------------------------------------
__device__ __forceinline__ unsigned f2tf(float x) {
    unsigned r;
    asm("cvt.rna.tf32.f32 %0, %1;" : "=r"(r) : "f"(x));
    return r;
}

__device__ __forceinline__ void mma_tf32(float* d, const unsigned* a,
                                         unsigned b0, unsigned b1) {
    asm volatile(
        "mma.sync.aligned.m16n8k8.row.col.f32.tf32.tf32.f32 "
        "{%0,%1,%2,%3}, {%4,%5,%6,%7}, {%8,%9}, {%0,%1,%2,%3};"
        : "+f"(d[0]), "+f"(d[1]), "+f"(d[2]), "+f"(d[3])
        : "r"(a[0]), "r"(a[1]), "r"(a[2]), "r"(a[3]), "r"(b0), "r"(b1));
}

// ---------------------------------------------------------------------------
// Tensor-core GEMM (tf32x3, error-compensated): C = A[M,E] @ W[E,E]^T + bias.
// 128x128 CTA tile, BK=16, 8 warps (4x2), warp tile 32x64, m16n8k8 mma.
// Smem row stride 20 (== 4 mod 32) -> fragment reads are conflict-free.
// SPLIT=true writes C into [B,H,S,D] layout, else row-major [M,E].
// ---------------------------------------------------------------------------
template<bool SPLIT>
__global__ __launch_bounds__(256) void gemm_tc_kernel(
    const float* __restrict__ A, const float* __restrict__ W,
    const float* __restrict__ bias, float* __restrict__ C)
{
    __shared__ unsigned As_hi[128][20];
    __shared__ unsigned As_lo[128][20];
    __shared__ unsigned Bs_hi[128][20];
    __shared__ unsigned Bs_lo[128][20];

    const int tid = threadIdx.x;
    const int bm = blockIdx.y * 128;
    const int bn = blockIdx.x * 128;

    const int warp = tid >> 5;
    const int lane = tid & 31;
    const int g = lane >> 2;        // groupID
    const int t = lane & 3;         // threadID_in_group
    const int warpRow = warp & 3;   // 4 row-warps of 32 rows
    const int warpCol = warp >> 2;  // 2 col-warps of 64 cols
    const int rb = warpRow * 32;
    const int cb = warpCol * 64;

    float acc[2][8][4];
#pragma unroll
    for (int mi = 0; mi < 2; mi++)
#pragma unroll
        for (int nj = 0; nj < 8; nj++)
#pragma unroll
            for (int c = 0; c < 4; c++) acc[mi][nj][c] = 0.f;

    for (int k0 = 0; k0 < E_; k0 += 16) {
#pragma unroll
        for (int i = 0; i < 2; i++) {
            int fid = tid + i * 256;          // 512 float4 per operand tile
            int r   = fid >> 2;               // 0..127
            int c4  = (fid & 3) * 4;          // 0,4,8,12
            float4 va = *(const float4*)(A + (size_t)(bm + r) * E_ + k0 + c4);
            {
                unsigned h0 = f2tf(va.x), h1 = f2tf(va.y), h2 = f2tf(va.z), h3 = f2tf(va.w);
                As_hi[r][c4+0] = h0; As_hi[r][c4+1] = h1; As_hi[r][c4+2] = h2; As_hi[r][c4+3] = h3;
                As_lo[r][c4+0] = f2tf(va.x - __uint_as_float(h0));
                As_lo[r][c4+1] = f2tf(va.y - __uint_as_float(h1));
                As_lo[r][c4+2] = f2tf(va.z - __uint_as_float(h2));
                As_lo[r][c4+3] = f2tf(va.w - __uint_as_float(h3));
            }
            float4 vb = *(const float4*)(W + (size_t)(bn + r) * E_ + k0 + c4);
            {
                unsigned h0 = f2tf(vb.x), h1 = f2tf(vb.y), h2 = f2tf(vb.z), h3 = f2tf(vb.w);
                Bs_hi[r][c4+0] = h0; Bs_hi[r][c4+1] = h1; Bs_hi[r][c4+2] = h2; Bs_hi[r][c4+3] = h3;
                Bs_lo[r][c4+0] = f2tf(vb.x - __uint_as_float(h0));
                Bs_lo[r][c4+1] = f2tf(vb.y - __uint_as_float(h1));
                Bs_lo[r][c4+2] = f2tf(vb.z - __uint_as_float(h2));
                Bs_lo[r][c4+3] = f2tf(vb.w - __uint_as_float(h3));
            }
        }
        __syncthreads();

#pragma unroll
        for (int kk = 0; kk < 2; kk++) {
            const int kb = kk * 8;
            unsigned ah[2][4], al[2][4];
#pragma unroll
            for (int mi = 0; mi < 2; mi++) {
                int r0 = rb + mi * 16 + g;
                ah[mi][0] = As_hi[r0    ][kb + t];
                ah[mi][1] = As_hi[r0 + 8][kb + t];
                ah[mi][2] = As_hi[r0    ][kb + t + 4];
                ah[mi][3] = As_hi[r0 + 8][kb + t + 4];
                al[mi][0] = As_lo[r0    ][kb + t];
                al[mi][1] = As_lo[r0 + 8][kb + t];
                al[mi][2] = As_lo[r0    ][kb + t + 4];
                al[mi][3] = As_lo[r0 + 8][kb + t + 4];
            }
#pragma unroll
            for (int nj = 0; nj < 8; nj++) {
                int nr = cb + nj * 8 + g;
                unsigned bh0 = Bs_hi[nr][kb + t];
                unsigned bh1 = Bs_hi[nr][kb + t + 4];
                unsigned bl0 = Bs_lo[nr][kb + t];
                unsigned bl1 = Bs_lo[nr][kb + t + 4];
#pragma unroll
                for (int mi = 0; mi < 2; mi++) {
                    mma_tf32(acc[mi][nj], ah[mi], bh0, bh1);   // hi*hi
                    mma_tf32(acc[mi][nj], ah[mi], bl0, bl1);   // hi*lo
                    mma_tf32(acc[mi][nj], al[mi], bh0, bh1);   // lo*hi
                }
            }
        }
        __syncthreads();
    }

    // epilogue: bias + store
    float2 brow[8];
#pragma unroll
    for (int nj = 0; nj < 8; nj++)
        brow[nj] = *(const float2*)(bias + bn + cb + nj * 8 + 2 * t);

#pragma unroll
    for (int mi = 0; mi < 2; mi++) {
#pragma unroll
        for (int nj = 0; nj < 8; nj++) {
            int m0 = bm + rb + mi * 16 + g;
            int m1 = m0 + 8;
            int n  = bn + cb + nj * 8 + 2 * t;
            float2 r0 = make_float2(acc[mi][nj][0] + brow[nj].x,
                                    acc[mi][nj][1] + brow[nj].y);
            float2 r1 = make_float2(acc[mi][nj][2] + brow[nj].x,
                                    acc[mi][nj][3] + brow[nj].y);
            if (SPLIT) {
                int h = n >> 6, d = n & 63;
                int b0i = m0 >> 11, s0 = m0 & (S_-1);
                int b1i = m1 >> 11, s1 = m1 & (S_-1);
                *(float2*)(C + ((size_t)(b0i * H_ + h) * S_ + s0) * D_ + d) = r0;
                *(float2*)(C + ((size_t)(b1i * H_ + h) * S_ + s1) * D_ + d) = r1;
            } else {
                *(float2*)(C + (size_t)m0 * E_ + n) = r0;
                *(float2*)(C + (size_t)m1 * E_ + n) = r1;
            }
        }
    }
}

// ---------------------------------------------------------------------------
// Causal flash attention, fp32 (unchanged from R1).
// ---------------------------------------------------------------------------
__global__ __launch_bounds__(256, 2) void attn_kernel()
{
    __shared__ float Qt[64][64];   // Qt[d][row]
    __shared__ float KP[64][64];   // Kt[d][col]  then  P[row][k]
    __shared__ float Vs[64][64];   // V[k][d]

    const int qt = blockIdx.x;
    const int bh = blockIdx.y;
    const int b  = bh >> 4;
    const int h  = bh & 15;
    const int tid = threadIdx.x;
    const int tx = tid & 15;
    const int ty = tid >> 4;

    const float* qbase = g_q + (size_t)bh * S_ * D_ + (size_t)qt * 64 * D_;
    const float* kbase = g_k + (size_t)bh * S_ * D_;
    const float* vbase = g_v + (size_t)bh * S_ * D_;

#pragma unroll
    for (int t = 0; t < 4; t++) {
        int fid = tid + t * 256;
        int row = fid & 63;
        int d4  = (fid >> 6) * 4;
        float4 v = *(const float4*)(qbase + row * D_ + d4);
        Qt[d4+0][row] = v.x; Qt[d4+1][row] = v.y; Qt[d4+2][row] = v.z; Qt[d4+3][row] = v.w;
    }

    float o[4][4];
    float m_i[4], l_i[4];
#pragma unroll
    for (int i = 0; i < 4; i++) {
        m_i[i] = -1e30f; l_i[i] = 0.f;
#pragma unroll
        for (int j = 0; j < 4; j++) o[i][j] = 0.f;
    }
    const float scale = 0.125f;

    for (int kt = 0; kt <= qt; kt++) {
        __syncthreads();
        const float* kb = kbase + (size_t)kt * 64 * D_;
        const float* vb = vbase + (size_t)kt * 64 * D_;
#pragma unroll
        for (int t = 0; t < 4; t++) {
            int fid = tid + t * 256;
            int col = fid & 63;
            int d4  = (fid >> 6) * 4;
            float4 v = *(const float4*)(kb + col * D_ + d4);
            KP[d4+0][col] = v.x; KP[d4+1][col] = v.y; KP[d4+2][col] = v.z; KP[d4+3][col] = v.w;
            int vr  = fid >> 4;
            int vc4 = (fid & 15) * 4;
            float4 w = *(const float4*)(vb + vr * D_ + vc4);
            *(float4*)&Vs[vr][vc4] = w;
        }
        __syncthreads();

        float s[4][4];
#pragma unroll
        for (int i = 0; i < 4; i++)
#pragma unroll
            for (int j = 0; j < 4; j++) s[i][j] = 0.f;
#pragma unroll
        for (int d = 0; d < 64; d++) {
            float4 a  = *(float4*)&Qt[d][ty*4];
            float4 bq = *(float4*)&KP[d][tx*4];
            s[0][0] = fmaf(a.x, bq.x, s[0][0]); s[0][1] = fmaf(a.x, bq.y, s[0][1]);
            s[0][2] = fmaf(a.x, bq.z, s[0][2]); s[0][3] = fmaf(a.x, bq.w, s[0][3]);
            s[1][0] = fmaf(a.y, bq.x, s[1][0]); s[1][1] = fmaf(a.y, bq.y, s[1][1]);
            s[1][2] = fmaf(a.y, bq.z, s[1][2]); s[1][3] = fmaf(a.y, bq.w, s[1][3]);
            s[2][0] = fmaf(a.z, bq.x, s[2][0]); s[2][1] = fmaf(a.z, bq.y, s[2][1]);
            s[2][2] = fmaf(a.z, bq.z, s[2][2]); s[2][3] = fmaf(a.z, bq.w, s[2][3]);
            s[3][0] = fmaf(a.w, bq.x, s[3][0]); s[3][1] = fmaf(a.w, bq.y, s[3][1]);
            s[3][2] = fmaf(a.w, bq.z, s[3][2]); s[3][3] = fmaf(a.w, bq.w, s[3][3]);
        }

#pragma unroll
        for (int i = 0; i < 4; i++)
#pragma unroll
            for (int j = 0; j < 4; j++) {
                float v = s[i][j] * scale;
                if (kt == qt && (tx*4 + j) > (ty*4 + i)) v = -1e30f;
                s[i][j] = v;
            }

        float alpha[4];
#pragma unroll
        for (int i = 0; i < 4; i++) {
            float r = fmaxf(fmaxf(s[i][0], s[i][1]), fmaxf(s[i][2], s[i][3]));
            r = fmaxf(r, __shfl_xor_sync(0xffffffffu, r, 1));
            r = fmaxf(r, __shfl_xor_sync(0xffffffffu, r, 2));
            r = fmaxf(r, __shfl_xor_sync(0xffffffffu, r, 4));
            r = fmaxf(r, __shfl_xor_sync(0xffffffffu, r, 8));
            float mnew = fmaxf(m_i[i], r);
            float ps = 0.f;
#pragma unroll
            for (int j = 0; j < 4; j++) {
                float p = __expf(s[i][j] - mnew);
                s[i][j] = p;
                ps += p;
            }
            ps += __shfl_xor_sync(0xffffffffu, ps, 1);
            ps += __shfl_xor_sync(0xffffffffu, ps, 2);
            ps += __shfl_xor_sync(0xffffffffu, ps, 4);
            ps += __shfl_xor_sync(0xffffffffu, ps, 8);
            alpha[i] = __expf(m_i[i] - mnew);
            l_i[i] = l_i[i] * alpha[i] + ps;
            m_i[i] = mnew;
        }
#pragma unroll
        for (int i = 0; i < 4; i++)
#pragma unroll
            for (int j = 0; j < 4; j++) o[i][j] *= alpha[i];

        __syncthreads();
#pragma unroll
        for (int i = 0; i < 4; i++) {
            float4 p4 = make_float4(s[i][0], s[i][1], s[i][2], s[i][3]);
            *(float4*)&KP[ty*4+i][tx*4] = p4;
        }
        __syncthreads();

#pragma unroll
        for (int k4 = 0; k4 < 16; k4++) {
            float4 bv0 = *(float4*)&Vs[k4*4+0][tx*4];
            float4 bv1 = *(float4*)&Vs[k4*4+1][tx*4];
            float4 bv2 = *(float4*)&Vs[k4*4+2][tx*4];
            float4 bv3 = *(float4*)&Vs[k4*4+3][tx*4];
#pragma unroll
            for (int i = 0; i < 4; i++) {
                float4 a = *(float4*)&KP[ty*4+i][k4*4];
                o[i][0] = fmaf(a.x, bv0.x, o[i][0]); o[i][1] = fmaf(a.x, bv0.y, o[i][1]);
                o[i][2] = fmaf(a.x, bv0.z, o[i][2]); o[i][3] = fmaf(a.x, bv0.w, o[i][3]);
                o[i][0] = fmaf(a.y, bv1.x, o[i][0]); o[i][1] = fmaf(a.y, bv1.y, o[i][1]);
                o[i][2] = fmaf(a.y, bv1.z, o[i][2]); o[i][3] = fmaf(a.y, bv1.w, o[i][3]);
                o[i][0] = fmaf(a.z, bv2.x, o[i][0]); o[i][1] = fmaf(a.z, bv2.y, o[i][1]);
                o[i][2] = fmaf(a.z, bv2.z, o[i][2]); o[i][3] = fmaf(a.z, bv2.w, o[i][3]);
                o[i][0] = fmaf(a.w, bv3.x, o[i][0]); o[i][1] = fmaf(a.w, bv3.y, o[i][1]);
                o[i][2] = fmaf(a.w, bv3.z, o[i][2]); o[i][3] = fmaf(a.w, bv3.w, o[i][3]);
            }
        }
    }

#pragma unroll
    for (int i = 0; i < 4; i++) {
        float inv = 1.f / l_i[i];
        int rowg = qt*64 + ty*4 + i;
        float4 r = make_float4(o[i][0]*inv, o[i][1]*inv, o[i][2]*inv, o[i][3]*inv);
        *(float4*)(g_attn + ((size_t)b * S_ + rowg) * E_ + h * D_ + tx*4) = r;
    }
}

// ---------------------------------------------------------------------------
extern "C" void kernel_launch(void* const* d_in, const int* in_sizes, int n_in,
                              void* d_out, int out_size)
{
    const float* Q  = (const float*)d_in[0];
    const float* K  = (const float*)d_in[1];
    const float* V  = (const float*)d_in[2];
    const float* Wq = (const float*)d_in[3];
    const float* bq = (const float*)d_in[4];
    const float* Wk = (const float*)d_in[5];
    const float* bk = (const float*)d_in[6];
    const float* Wv = (const float*)d_in[7];
    const float* bv = (const float*)d_in[8];
    const float* Wo = (const float*)d_in[9];
    const float* bo = (const float*)d_in[10];
    // d_in[11] = mask: tril -> causal handled analytically

    float *qb, *kb, *vb, *ab;
    cudaGetSymbolAddress((void**)&qb, g_q);
    cudaGetSymbolAddress((void**)&kb, g_k);
    cudaGetSymbolAddress((void**)&vb, g_v);
    cudaGetSymbolAddress((void**)&ab, g_attn);

    dim3 gg(E_/128, M_/128);     // (8, 32)
    dim3 blk(256);
    gemm_tc_kernel<true><<<gg, blk>>>(Q, Wq, bq, qb);
    gemm_tc_kernel<true><<<gg, blk>>>(K, Wk, bk, kb);
    gemm_tc_kernel<true><<<gg, blk>>>(V, Wv, bv, vb);
    attn_kernel<<<dim3(S_/64, B_*H_), blk>>>();
    gemm_tc_kernel<false><<<gg, blk>>>(ab, Wo, bo, (float*)d_out);
}

// round 3
// speedup vs baseline: 2.0150x; 2.0150x over previous
#include <cuda_runtime.h>
#include <cuda_bf16.h>
#include <math.h>

#define B_ 2
#define S_ 2048
#define E_ 1024
#define H_ 16
#define D_ 64
#define M_ (B_*S_)     // 4096
#define NBSE (B_*S_*E_)   // 4M
#define NBHSD (B_*H_*S_*D_) // 4M
#define NEE (E_*E_)       // 1M

// ---------------- scratch (allocation-free) ----------------
__device__ __nv_bfloat16 g_xqh[NBSE], g_xql[NBSE], g_xkh[NBSE], g_xkl[NBSE], g_xvh[NBSE], g_xvl[NBSE];
__device__ __nv_bfloat16 g_wqh[NEE], g_wql[NEE], g_wkh[NEE], g_wkl[NEE];
__device__ __nv_bfloat16 g_wvh[NEE], g_wvl[NEE], g_woh[NEE], g_wol[NEE];
__device__ __nv_bfloat16 g_qh[NBHSD], g_ql[NBHSD], g_kh[NBHSD], g_kl[NBHSD], g_vh[NBHSD], g_vl[NBHSD];
__device__ __nv_bfloat16 g_vth[NBHSD], g_vtl[NBHSD];   // V transposed [B,H,D,S]
__device__ __nv_bfloat16 g_ah[NBSE], g_al[NBSE];       // attention output hi/lo

// ---------------- helpers ----------------
__device__ __forceinline__ void mma_bf16(float* d, const unsigned* a, unsigned b0, unsigned b1) {
    asm volatile(
        "mma.sync.aligned.m16n8k16.row.col.f32.bf16.bf16.f32 "
        "{%0,%1,%2,%3}, {%4,%5,%6,%7}, {%8,%9}, {%0,%1,%2,%3};"
        : "+f"(d[0]), "+f"(d[1]), "+f"(d[2]), "+f"(d[3])
        : "r"(a[0]), "r"(a[1]), "r"(a[2]), "r"(a[3]), "r"(b0), "r"(b1));
}

__device__ __forceinline__ void split_pack(float x, float y, unsigned& h, unsigned& l) {
    __nv_bfloat16 hx = __float2bfloat16_rn(x), hy = __float2bfloat16_rn(y);
    __nv_bfloat16 lx = __float2bfloat16_rn(x - __bfloat162float(hx));
    __nv_bfloat16 ly = __float2bfloat16_rn(y - __bfloat162float(hy));
    __nv_bfloat162 H = __halves2bfloat162(hx, hy);
    __nv_bfloat162 L = __halves2bfloat162(lx, ly);
    h = *reinterpret_cast<unsigned*>(&H);
    l = *reinterpret_cast<unsigned*>(&L);
}

// ---------------- one-time f32 -> bf16 hi/lo split ----------------
__global__ void split_kernel(const float4* __restrict__ x,
                             __nv_bfloat162* __restrict__ hi,
                             __nv_bfloat162* __restrict__ lo, int n4) {
    int i = blockIdx.x * blockDim.x + threadIdx.x;
    if (i >= n4) return;
    float4 v = x[i];
    unsigned h0, l0, h1, l1;
    split_pack(v.x, v.y, h0, l0);
    split_pack(v.z, v.w, h1, l1);
    hi[2*i]   = *reinterpret_cast<__nv_bfloat162*>(&h0);
    hi[2*i+1] = *reinterpret_cast<__nv_bfloat162*>(&h1);
    lo[2*i]   = *reinterpret_cast<__nv_bfloat162*>(&l0);
    lo[2*i+1] = *reinterpret_cast<__nv_bfloat162*>(&l1);
}

// ---------------- V transpose [B,H,S,D] -> [B,H,D,S] (hi+lo) ----------------
__global__ void transpose_v_kernel(const __nv_bfloat16* __restrict__ vh,
                                   const __nv_bfloat16* __restrict__ vl,
                                   __nv_bfloat16* __restrict__ vth,
                                   __nv_bfloat16* __restrict__ vtl) {
    __shared__ __nv_bfloat16 th[32][33], tl[32][33];
    int bh = blockIdx.z;
    int s0 = blockIdx.x * 32;
    int d0 = blockIdx.y * 32;
    size_t base = (size_t)bh * S_ * D_;
#pragma unroll
    for (int i = 0; i < 4; i++) {
        int r = threadIdx.y + i * 8;
        th[r][threadIdx.x] = vh[base + (size_t)(s0 + r) * D_ + d0 + threadIdx.x];
        tl[r][threadIdx.x] = vl[base + (size_t)(s0 + r) * D_ + d0 + threadIdx.x];
    }
    __syncthreads();
#pragma unroll
    for (int i = 0; i < 4; i++) {
        int r = threadIdx.y + i * 8;
        vth[base + (size_t)(d0 + r) * S_ + s0 + threadIdx.x] = th[threadIdx.x][r];
        vtl[base + (size_t)(d0 + r) * S_ + s0 + threadIdx.x] = tl[threadIdx.x][r];
    }
}

// ---------------------------------------------------------------------------
// bf16x3 tensor-core GEMM: C = A[M,E] @ W[E,E]^T + bias.
// 128x128 tile, BK=32, 8 warps (4x2), warp tile 32x64, m16n8k16 bf16 mma.
// Smem row stride 40 bf16 (20 words, ==20 mod 32 -> conflict-free frags).
// MODE 0: f32 row-major out.  MODE 1: bf16 hi/lo out in [B,H,S,D].
// ---------------------------------------------------------------------------
template<int MODE>
__global__ __launch_bounds__(256) void gemm_bf16_kernel(
    const __nv_bfloat16* __restrict__ Ah, const __nv_bfloat16* __restrict__ Al,
    const __nv_bfloat16* __restrict__ Wh, const __nv_bfloat16* __restrict__ Wl,
    const float* __restrict__ bias, float* __restrict__ Cf,
    __nv_bfloat16* __restrict__ Ch, __nv_bfloat16* __restrict__ Cl)
{
    __shared__ unsigned As_hi[128][20];   // 40 bf16 per row (32 + 8 pad)
    __shared__ unsigned As_lo[128][20];
    __shared__ unsigned Bs_hi[128][20];
    __shared__ unsigned Bs_lo[128][20];

    const int tid = threadIdx.x;
    const int bm = blockIdx.y * 128;
    const int bn = blockIdx.x * 128;
    const int warp = tid >> 5;
    const int lane = tid & 31;
    const int g = lane >> 2;
    const int t = lane & 3;
    const int rb = (warp & 3) * 32;
    const int cb = (warp >> 2) * 64;

    float acc[2][8][4];
#pragma unroll
    for (int mi = 0; mi < 2; mi++)
#pragma unroll
        for (int nj = 0; nj < 8; nj++)
#pragma unroll
            for (int c = 0; c < 4; c++) acc[mi][nj][c] = 0.f;

    for (int k0 = 0; k0 < E_; k0 += 32) {
#pragma unroll
        for (int i = 0; i < 2; i++) {
            int fid = tid + i * 256;
            int r   = fid >> 2;
            int q   = fid & 3;
            size_t ga = (size_t)(bm + r) * E_ + k0 + q * 8;
            size_t gb = (size_t)(bn + r) * E_ + k0 + q * 8;
            *(uint4*)&As_hi[r][q*4] = *(const uint4*)(Ah + ga);
            *(uint4*)&As_lo[r][q*4] = *(const uint4*)(Al + ga);
            *(uint4*)&Bs_hi[r][q*4] = *(const uint4*)(Wh + gb);
            *(uint4*)&Bs_lo[r][q*4] = *(const uint4*)(Wl + gb);
        }
        __syncthreads();

#pragma unroll
        for (int kk = 0; kk < 2; kk++) {
            const int kw = kk * 8;
            unsigned ah[2][4], al[2][4];
#pragma unroll
            for (int mi = 0; mi < 2; mi++) {
                int r0 = rb + mi * 16 + g;
                ah[mi][0] = As_hi[r0    ][kw + t];
                ah[mi][1] = As_hi[r0 + 8][kw + t];
                ah[mi][2] = As_hi[r0    ][kw + t + 4];
                ah[mi][3] = As_hi[r0 + 8][kw + t + 4];
                al[mi][0] = As_lo[r0    ][kw + t];
                al[mi][1] = As_lo[r0 + 8][kw + t];
                al[mi][2] = As_lo[r0    ][kw + t + 4];
                al[mi][3] = As_lo[r0 + 8][kw + t + 4];
            }
#pragma unroll
            for (int nj = 0; nj < 8; nj++) {
                int nr = cb + nj * 8 + g;
                unsigned bh0 = Bs_hi[nr][kw + t];
                unsigned bh1 = Bs_hi[nr][kw + t + 4];
                unsigned bl0 = Bs_lo[nr][kw + t];
                unsigned bl1 = Bs_lo[nr][kw + t + 4];
#pragma unroll
                for (int mi = 0; mi < 2; mi++) {
                    mma_bf16(acc[mi][nj], ah[mi], bh0, bh1);
                    mma_bf16(acc[mi][nj], ah[mi], bl0, bl1);
                    mma_bf16(acc[mi][nj], al[mi], bh0, bh1);
                }
            }
        }
        __syncthreads();
    }

    // epilogue
#pragma unroll
    for (int mi = 0; mi < 2; mi++) {
#pragma unroll
        for (int nj = 0; nj < 8; nj++) {
            int m0 = bm + rb + mi * 16 + g;
            int m1 = m0 + 8;
            int n  = bn + cb + nj * 8 + 2 * t;
            float2 bv = *(const float2*)(bias + n);
            float2 r0 = make_float2(acc[mi][nj][0] + bv.x, acc[mi][nj][1] + bv.y);
            float2 r1 = make_float2(acc[mi][nj][2] + bv.x, acc[mi][nj][3] + bv.y);
            if (MODE == 1) {
                int h = n >> 6, d = n & 63;
                int b0i = m0 >> 11, s0 = m0 & (S_-1);
                int b1i = m1 >> 11, s1 = m1 & (S_-1);
                size_t a0 = ((size_t)(b0i * H_ + h) * S_ + s0) * D_ + d;
                size_t a1 = ((size_t)(b1i * H_ + h) * S_ + s1) * D_ + d;
                unsigned h0, l0, h1, l1;
                split_pack(r0.x, r0.y, h0, l0);
                split_pack(r1.x, r1.y, h1, l1);
                *(unsigned*)(Ch + a0) = h0; *(unsigned*)(Cl + a0) = l0;
                *(unsigned*)(Ch + a1) = h1; *(unsigned*)(Cl + a1) = l1;
            } else {
                *(float2*)(Cf + (size_t)m0 * E_ + n) = r0;
                *(float2*)(Cf + (size_t)m1 * E_ + n) = r1;
            }
        }
    }
}

// ---------------------------------------------------------------------------
// Causal flash attention on tensor cores (bf16x3).
// Block = 4 warps, 64 q-rows (16/warp). Key tile = 64. P stays in registers.
// Smem stride 72 bf16 (36 words, ==4 mod 32 -> conflict-free frags).
// ---------------------------------------------------------------------------
__global__ __launch_bounds__(128) void attn_tc_kernel(
    const __nv_bfloat16* __restrict__ qh, const __nv_bfloat16* __restrict__ ql,
    const __nv_bfloat16* __restrict__ kh, const __nv_bfloat16* __restrict__ kl,
    const __nv_bfloat16* __restrict__ vth, const __nv_bfloat16* __restrict__ vtl,
    __nv_bfloat16* __restrict__ oh, __nv_bfloat16* __restrict__ ol)
{
    __shared__ unsigned Ks_hi[64][36];
    __shared__ unsigned Ks_lo[64][36];
    __shared__ unsigned Vt_hi[64][36];
    __shared__ unsigned Vt_lo[64][36];

    const int qt = (gridDim.x - 1) - blockIdx.x;   // heavy tiles first
    const int bh = blockIdx.y;
    const int b  = bh >> 4;
    const int h  = bh & 15;
    const int tid  = threadIdx.x;
    const int warp = tid >> 5;
    const int lane = tid & 31;
    const int g = lane >> 2;
    const int t = lane & 3;

    const size_t qkbase = (size_t)bh * S_ * D_;
    const size_t vtbase = (size_t)bh * D_ * S_;
    const int r0 = qt * 64 + warp * 16 + g;   // global q row
    const int r1 = r0 + 8;

    // Q fragments (hi/lo), k = d in 4 chunks of 16
    unsigned qfh[4][4], qfl[4][4];
    {
        const unsigned* q0h = (const unsigned*)(qh + qkbase + (size_t)r0 * D_);
        const unsigned* q1h = (const unsigned*)(qh + qkbase + (size_t)r1 * D_);
        const unsigned* q0l = (const unsigned*)(ql + qkbase + (size_t)r0 * D_);
        const unsigned* q1l = (const unsigned*)(ql + qkbase + (size_t)r1 * D_);
#pragma unroll
        for (int kk = 0; kk < 4; kk++) {
            qfh[kk][0] = q0h[kk*8 + t];     qfh[kk][1] = q1h[kk*8 + t];
            qfh[kk][2] = q0h[kk*8 + t + 4]; qfh[kk][3] = q1h[kk*8 + t + 4];
            qfl[kk][0] = q0l[kk*8 + t];     qfl[kk][1] = q1l[kk*8 + t];
            qfl[kk][2] = q0l[kk*8 + t + 4]; qfl[kk][3] = q1l[kk*8 + t + 4];
        }
    }

    float o[8][4];
#pragma unroll
    for (int j = 0; j < 8; j++)
#pragma unroll
        for (int c = 0; c < 4; c++) o[j][c] = 0.f;
    float mrow[2] = {-1e30f, -1e30f};
    float lrow[2] = {0.f, 0.f};
    const float scale = 0.125f;

    for (int kt = 0; kt <= qt; kt++) {
        __syncthreads();
#pragma unroll
        for (int i = 0; i < 4; i++) {
            int fid = tid + i * 128;
            int row = fid >> 3;          // key index (K) / d index (Vt)
            int q8  = (fid & 7) * 8;     // bf16 col offset
            size_t gk = qkbase + (size_t)(kt * 64 + row) * D_ + q8;
            *(uint4*)&Ks_hi[row][(fid & 7) * 4] = *(const uint4*)(kh + gk);
            *(uint4*)&Ks_lo[row][(fid & 7) * 4] = *(const uint4*)(kl + gk);
            size_t gv = vtbase + (size_t)row * S_ + kt * 64 + q8;
            *(uint4*)&Vt_hi[row][(fid & 7) * 4] = *(const uint4*)(vth + gv);
            *(uint4*)&Vt_lo[row][(fid & 7) * 4] = *(const uint4*)(vtl + gv);
        }
        __syncthreads();

        // scores: m16 x 64 keys, contract over d=64
        float s[8][4];
#pragma unroll
        for (int j = 0; j < 8; j++)
#pragma unroll
            for (int c = 0; c < 4; c++) s[j][c] = 0.f;
#pragma unroll
        for (int kk = 0; kk < 4; kk++) {
            const int kw = kk * 8;
#pragma unroll
            for (int nj = 0; nj < 8; nj++) {
                int nr = nj * 8 + g;
                unsigned bh0 = Ks_hi[nr][kw + t];
                unsigned bh1 = Ks_hi[nr][kw + t + 4];
                unsigned bl0 = Ks_lo[nr][kw + t];
                unsigned bl1 = Ks_lo[nr][kw + t + 4];
                mma_bf16(s[nj], qfh[kk], bh0, bh1);
                mma_bf16(s[nj], qfh[kk], bl0, bl1);
                mma_bf16(s[nj], qfl[kk], bh0, bh1);
            }
        }

        // scale + causal mask (diagonal tile only)
#pragma unroll
        for (int nj = 0; nj < 8; nj++) {
            int c0 = kt * 64 + nj * 8 + 2 * t;
            s[nj][0] *= scale; s[nj][1] *= scale;
            s[nj][2] *= scale; s[nj][3] *= scale;
            if (kt == qt) {
                if (c0     > r0) s[nj][0] = -1e30f;
                if (c0 + 1 > r0) s[nj][1] = -1e30f;
                if (c0     > r1) s[nj][2] = -1e30f;
                if (c0 + 1 > r1) s[nj][3] = -1e30f;
            }
        }

        // online softmax (2 rows per thread; quad reduce over t lanes)
        float rm0 = -1e30f, rm1 = -1e30f;
#pragma unroll
        for (int nj = 0; nj < 8; nj++) {
            rm0 = fmaxf(rm0, fmaxf(s[nj][0], s[nj][1]));
            rm1 = fmaxf(rm1, fmaxf(s[nj][2], s[nj][3]));
        }
        rm0 = fmaxf(rm0, __shfl_xor_sync(0xffffffffu, rm0, 1));
        rm0 = fmaxf(rm0, __shfl_xor_sync(0xffffffffu, rm0, 2));
        rm1 = fmaxf(rm1, __shfl_xor_sync(0xffffffffu, rm1, 1));
        rm1 = fmaxf(rm1, __shfl_xor_sync(0xffffffffu, rm1, 2));
        float mn0 = fmaxf(mrow[0], rm0);
        float mn1 = fmaxf(mrow[1], rm1);
        float a0 = __expf(mrow[0] - mn0);
        float a1 = __expf(mrow[1] - mn1);
        float ps0 = 0.f, ps1 = 0.f;
#pragma unroll
        for (int nj = 0; nj < 8; nj++) {
            s[nj][0] = __expf(s[nj][0] - mn0);
            s[nj][1] = __expf(s[nj][1] - mn0);
            s[nj][2] = __expf(s[nj][2] - mn1);
            s[nj][3] = __expf(s[nj][3] - mn1);
            ps0 += s[nj][0] + s[nj][1];
            ps1 += s[nj][2] + s[nj][3];
        }
        ps0 += __shfl_xor_sync(0xffffffffu, ps0, 1);
        ps0 += __shfl_xor_sync(0xffffffffu, ps0, 2);
        ps1 += __shfl_xor_sync(0xffffffffu, ps1, 1);
        ps1 += __shfl_xor_sync(0xffffffffu, ps1, 2);
        lrow[0] = lrow[0] * a0 + ps0;
        lrow[1] = lrow[1] * a1 + ps1;
        mrow[0] = mn0; mrow[1] = mn1;
#pragma unroll
        for (int j = 0; j < 8; j++) {
            o[j][0] *= a0; o[j][1] *= a0;
            o[j][2] *= a1; o[j][3] *= a1;
        }

        // P·V: pack P into A-fragments (hi/lo), contract over 64 keys
#pragma unroll
        for (int kk = 0; kk < 4; kk++) {
            unsigned pa[4], pl[4];
            split_pack(s[2*kk  ][0], s[2*kk  ][1], pa[0], pl[0]);
            split_pack(s[2*kk  ][2], s[2*kk  ][3], pa[1], pl[1]);
            split_pack(s[2*kk+1][0], s[2*kk+1][1], pa[2], pl[2]);
            split_pack(s[2*kk+1][2], s[2*kk+1][3], pa[3], pl[3]);
            const int kw = kk * 8;
#pragma unroll
            for (int jd = 0; jd < 8; jd++) {
                int nr = jd * 8 + g;
                unsigned bh0 = Vt_hi[nr][kw + t];
                unsigned bh1 = Vt_hi[nr][kw + t + 4];
                unsigned bl0 = Vt_lo[nr][kw + t];
                unsigned bl1 = Vt_lo[nr][kw + t + 4];
                mma_bf16(o[jd], pa, bh0, bh1);
                mma_bf16(o[jd], pa, bl0, bl1);
                mma_bf16(o[jd], pl, bh0, bh1);
            }
        }
    }

    // epilogue: normalize, split to bf16 hi/lo, write [B,S,E]
    float inv0 = 1.f / lrow[0];
    float inv1 = 1.f / lrow[1];
#pragma unroll
    for (int jd = 0; jd < 8; jd++) {
        int e = h * D_ + jd * 8 + 2 * t;
        size_t ad0 = ((size_t)b * S_ + r0) * E_ + e;
        size_t ad1 = ((size_t)b * S_ + r1) * E_ + e;
        unsigned h0, l0, h1, l1;
        split_pack(o[jd][0] * inv0, o[jd][1] * inv0, h0, l0);
        split_pack(o[jd][2] * inv1, o[jd][3] * inv1, h1, l1);
        *(unsigned*)(oh + ad0) = h0; *(unsigned*)(ol + ad0) = l0;
        *(unsigned*)(oh + ad1) = h1; *(unsigned*)(ol + ad1) = l1;
    }
}

// ---------------------------------------------------------------------------
extern "C" void kernel_launch(void* const* d_in, const int* in_sizes, int n_in,
                              void* d_out, int out_size)
{
    const float* Q  = (const float*)d_in[0];
    const float* K  = (const float*)d_in[1];
    const float* V  = (const float*)d_in[2];
    const float* Wq = (const float*)d_in[3];
    const float* bq = (const float*)d_in[4];
    const float* Wk = (const float*)d_in[5];
    const float* bk = (const float*)d_in[6];
    const float* Wv = (const float*)d_in[7];
    const float* bv = (const float*)d_in[8];
    const float* Wo = (const float*)d_in[9];
    const float* bo = (const float*)d_in[10];

    __nv_bfloat16 *xqh,*xql,*xkh,*xkl,*xvh,*xvl;
    __nv_bfloat16 *wqh,*wql,*wkh,*wkl,*wvh,*wvl,*woh,*wol;
    __nv_bfloat16 *qh,*ql,*kh,*kl,*vh,*vl,*vth,*vtl,*ah,*al;
    cudaGetSymbolAddress((void**)&xqh, g_xqh); cudaGetSymbolAddress((void**)&xql, g_xql);
    cudaGetSymbolAddress((void**)&xkh, g_xkh); cudaGetSymbolAddress((void**)&xkl, g_xkl);
    cudaGetSymbolAddress((void**)&xvh, g_xvh); cudaGetSymbolAddress((void**)&xvl, g_xvl);
    cudaGetSymbolAddress((void**)&wqh, g_wqh); cudaGetSymbolAddress((void**)&wql, g_wql);
    cudaGetSymbolAddress((void**)&wkh, g_wkh); cudaGetSymbolAddress((void**)&wkl, g_wkl);
    cudaGetSymbolAddress((void**)&wvh, g_wvh); cudaGetSymbolAddress((void**)&wvl, g_wvl);
    cudaGetSymbolAddress((void**)&woh, g_woh); cudaGetSymbolAddress((void**)&wol, g_wol);
    cudaGetSymbolAddress((void**)&qh, g_qh);   cudaGetSymbolAddress((void**)&ql, g_ql);
    cudaGetSymbolAddress((void**)&kh, g_kh);   cudaGetSymbolAddress((void**)&kl, g_kl);
    cudaGetSymbolAddress((void**)&vh, g_vh);   cudaGetSymbolAddress((void**)&vl, g_vl);
    cudaGetSymbolAddress((void**)&vth, g_vth); cudaGetSymbolAddress((void**)&vtl, g_vtl);
    cudaGetSymbolAddress((void**)&ah, g_ah);   cudaGetSymbolAddress((void**)&al, g_al);

    const int n4x = NBSE / 4;   // 1M
    const int n4w = NEE / 4;    // 256K
    split_kernel<<<n4x/256, 256>>>((const float4*)Q,  (__nv_bfloat162*)xqh, (__nv_bfloat162*)xql, n4x);
    split_kernel<<<n4x/256, 256>>>((const float4*)K,  (__nv_bfloat162*)xkh, (__nv_bfloat162*)xkl, n4x);
    split_kernel<<<n4x/256, 256>>>((const float4*)V,  (__nv_bfloat162*)xvh, (__nv_bfloat162*)xvl, n4x);
    split_kernel<<<n4w/256, 256>>>((const float4*)Wq, (__nv_bfloat162*)wqh, (__nv_bfloat162*)wql, n4w);
    split_kernel<<<n4w/256, 256>>>((const float4*)Wk, (__nv_bfloat162*)wkh, (__nv_bfloat162*)wkl, n4w);
    split_kernel<<<n4w/256, 256>>>((const float4*)Wv, (__nv_bfloat162*)wvh, (__nv_bfloat162*)wvl, n4w);
    split_kernel<<<n4w/256, 256>>>((const float4*)Wo, (__nv_bfloat162*)woh, (__nv_bfloat162*)wol, n4w);

    dim3 gg(E_/128, M_/128);   // (8, 32)
    gemm_bf16_kernel<1><<<gg, 256>>>(xqh, xql, wqh, wql, bq, nullptr, qh, ql);
    gemm_bf16_kernel<1><<<gg, 256>>>(xkh, xkl, wkh, wkl, bk, nullptr, kh, kl);
    gemm_bf16_kernel<1><<<gg, 256>>>(xvh, xvl, wvh, wvl, bv, nullptr, vh, vl);

    transpose_v_kernel<<<dim3(S_/32, D_/32, B_*H_), dim3(32, 8)>>>(vh, vl, vth, vtl);

    attn_tc_kernel<<<dim3(S_/64, B_*H_), 128>>>(qh, ql, kh, kl, vth, vtl, ah, al);

    gemm_bf16_kernel<0><<<gg, 256>>>(ah, al, woh, wol, bo, (float*)d_out, nullptr, nullptr);
}

// round 4
// speedup vs baseline: 2.4821x; 1.2318x over previous
#include <cuda_runtime.h>
#include <cuda_bf16.h>
#include <math.h>

#define B_ 2
#define S_ 2048
#define E_ 1024
#define H_ 16
#define D_ 64
#define M_ (B_*S_)     // 4096
#define NBSE (B_*S_*E_)   // 4M
#define NBHSD (B_*H_*S_*D_) // 4M
#define NEE (E_*E_)       // 1M

// ---------------- scratch (allocation-free) ----------------
__device__ __nv_bfloat16 g_xqh[NBSE], g_xql[NBSE], g_xkh[NBSE], g_xkl[NBSE], g_xvh[NBSE], g_xvl[NBSE];
__device__ __nv_bfloat16 g_wqh[NEE], g_wql[NEE], g_wkh[NEE], g_wkl[NEE];
__device__ __nv_bfloat16 g_wvh[NEE], g_wvl[NEE], g_woh[NEE], g_wol[NEE];
__device__ __nv_bfloat16 g_qh[NBHSD], g_ql[NBHSD], g_kh[NBHSD], g_kl[NBHSD], g_vh[NBHSD], g_vl[NBHSD];
__device__ __nv_bfloat16 g_vth[NBHSD], g_vtl[NBHSD];   // V transposed [B,H,D,S]
__device__ __nv_bfloat16 g_ah[NBSE], g_al[NBSE];       // attention output hi/lo

// ---------------- helpers ----------------
__device__ __forceinline__ void mma_bf16(float* d, const unsigned* a, unsigned b0, unsigned b1) {
    asm volatile(
        "mma.sync.aligned.m16n8k16.row.col.f32.bf16.bf16.f32 "
        "{%0,%1,%2,%3}, {%4,%5,%6,%7}, {%8,%9}, {%0,%1,%2,%3};"
        : "+f"(d[0]), "+f"(d[1]), "+f"(d[2]), "+f"(d[3])
        : "r"(a[0]), "r"(a[1]), "r"(a[2]), "r"(a[3]), "r"(b0), "r"(b1));
}

__device__ __forceinline__ void ldsm_x4(unsigned* r, unsigned addr) {
    asm volatile("ldmatrix.sync.aligned.m8n8.x4.shared.b16 {%0,%1,%2,%3}, [%4];"
                 : "=r"(r[0]), "=r"(r[1]), "=r"(r[2]), "=r"(r[3]) : "r"(addr));
}

__device__ __forceinline__ void cp_async16(unsigned saddr, const void* gptr) {
    asm volatile("cp.async.cg.shared.global [%0], [%1], 16;" :: "r"(saddr), "l"(gptr));
}
__device__ __forceinline__ void cp_commit() { asm volatile("cp.async.commit_group;"); }
__device__ __forceinline__ void cp_wait1()  { asm volatile("cp.async.wait_group 1;"); }

__device__ __forceinline__ unsigned s2u(const void* p) {
    return (unsigned)__cvta_generic_to_shared(p);
}

__device__ __forceinline__ void split_pack(float x, float y, unsigned& h, unsigned& l) {
    __nv_bfloat16 hx = __float2bfloat16_rn(x), hy = __float2bfloat16_rn(y);
    __nv_bfloat16 lx = __float2bfloat16_rn(x - __bfloat162float(hx));
    __nv_bfloat16 ly = __float2bfloat16_rn(y - __bfloat162float(hy));
    __nv_bfloat162 H = __halves2bfloat162(hx, hy);
    __nv_bfloat162 L = __halves2bfloat162(lx, ly);
    h = *reinterpret_cast<unsigned*>(&H);
    l = *reinterpret_cast<unsigned*>(&L);
}

// ---------------- one-time f32 -> bf16 hi/lo split ----------------
__global__ void split_kernel(const float4* __restrict__ x,
                             __nv_bfloat162* __restrict__ hi,
                             __nv_bfloat162* __restrict__ lo, int n4) {
    int i = blockIdx.x * blockDim.x + threadIdx.x;
    if (i >= n4) return;
    float4 v = x[i];
    unsigned h0, l0, h1, l1;
    split_pack(v.x, v.y, h0, l0);
    split_pack(v.z, v.w, h1, l1);
    hi[2*i]   = *reinterpret_cast<__nv_bfloat162*>(&h0);
    hi[2*i+1] = *reinterpret_cast<__nv_bfloat162*>(&h1);
    lo[2*i]   = *reinterpret_cast<__nv_bfloat162*>(&l0);
    lo[2*i+1] = *reinterpret_cast<__nv_bfloat162*>(&l1);
}

// ---------------- V transpose [B,H,S,D] -> [B,H,D,S] (hi+lo) ----------------
__global__ void transpose_v_kernel(const __nv_bfloat16* __restrict__ vh,
                                   const __nv_bfloat16* __restrict__ vl,
                                   __nv_bfloat16* __restrict__ vth,
                                   __nv_bfloat16* __restrict__ vtl) {
    __shared__ __nv_bfloat16 th[32][33], tl[32][33];
    int bh = blockIdx.z;
    int s0 = blockIdx.x * 32;
    int d0 = blockIdx.y * 32;
    size_t base = (size_t)bh * S_ * D_;
#pragma unroll
    for (int i = 0; i < 4; i++) {
        int r = threadIdx.y + i * 8;
        th[r][threadIdx.x] = vh[base + (size_t)(s0 + r) * D_ + d0 + threadIdx.x];
        tl[r][threadIdx.x] = vl[base + (size_t)(s0 + r) * D_ + d0 + threadIdx.x];
    }
    __syncthreads();
#pragma unroll
    for (int i = 0; i < 4; i++) {
        int r = threadIdx.y + i * 8;
        vth[base + (size_t)(d0 + r) * S_ + s0 + threadIdx.x] = th[threadIdx.x][r];
        vtl[base + (size_t)(d0 + r) * S_ + s0 + threadIdx.x] = tl[threadIdx.x][r];
    }
}

// ---------------------------------------------------------------------------
// bf16x3 tensor-core GEMM: C = A[M,E] @ W[E,E]^T + bias.
// 128x128 tile, BK=32, 8 warps (4x2), m16n8k16, ldmatrix frags,
// 2-stage cp.async double buffer in dynamic smem (80KB).
// Stage layout (words): As_hi[0], As_lo[2560], Bs_hi[5120], Bs_lo[7680];
// row stride 20 words (conflict-free LDSM: 20r mod 32 partitions banks).
// MODE 0: f32 row-major out.  MODE 1: bf16 hi/lo out in [B,H,S,D].
// ---------------------------------------------------------------------------
#define STG_W 10240          // words per stage
#define ROW_W 20             // words per smem row

template<int MODE>
__global__ __launch_bounds__(256) void gemm_bf16_kernel(
    const __nv_bfloat16* __restrict__ Ah, const __nv_bfloat16* __restrict__ Al,
    const __nv_bfloat16* __restrict__ Wh, const __nv_bfloat16* __restrict__ Wl,
    const float* __restrict__ bias, float* __restrict__ Cf,
    __nv_bfloat16* __restrict__ Ch, __nv_bfloat16* __restrict__ Cl)
{
    extern __shared__ unsigned smem_dyn[];
    const unsigned sbase = s2u(smem_dyn);

    const int tid = threadIdx.x;
    const int bm = blockIdx.y * 128;
    const int bn = blockIdx.x * 128;
    const int warp = tid >> 5;
    const int lane = tid & 31;
    const int g = lane >> 2;
    const int t = lane & 3;
    const int rb = (warp & 3) * 32;
    const int cb = (warp >> 2) * 64;

    // cp.async mapping: 2 chunks of 16B per array per thread
    const int r_ld  = tid >> 2;          // 0..63 (+64 with i=1)
    const int q_ld  = tid & 3;           // 16B chunk within 32-col row

    // ldmatrix per-lane offsets
    const int arow  = (lane & 7) + ((lane >> 3) & 1) * 8;
    const int acolw = (lane >> 4) * 4;
    const unsigned aoff = (unsigned)(arow * ROW_W + acolw) * 4;
    const int brow  = ((lane >> 4) * 8) + (lane & 7);
    const int bcolw = ((lane >> 3) & 1) * 4;
    const unsigned boff = (unsigned)(brow * ROW_W + bcolw) * 4;

    float acc[2][8][4];
#pragma unroll
    for (int mi = 0; mi < 2; mi++)
#pragma unroll
        for (int nj = 0; nj < 8; nj++)
#pragma unroll
            for (int c = 0; c < 4; c++) acc[mi][nj][c] = 0.f;

    auto load_stage = [&](int stage, int k0) {
        unsigned sb = sbase + (unsigned)stage * (STG_W * 4);
#pragma unroll
        for (int i = 0; i < 2; i++) {
            int r = r_ld + i * 64;
            unsigned woff = (unsigned)(r * ROW_W + q_ld * 4) * 4;
            size_t ga = (size_t)(bm + r) * E_ + k0 + q_ld * 8;
            size_t gb = (size_t)(bn + r) * E_ + k0 + q_ld * 8;
            cp_async16(sb + woff,             Ah + ga);
            cp_async16(sb + 2560*4 + woff,    Al + ga);
            cp_async16(sb + 5120*4 + woff,    Wh + gb);
            cp_async16(sb + 7680*4 + woff,    Wl + gb);
        }
    };

    const int KT = E_ / 32;   // 32
    load_stage(0, 0);
    cp_commit();

    for (int it = 0; it < KT; it++) {
        if (it + 1 < KT) load_stage((it + 1) & 1, (it + 1) * 32);
        cp_commit();
        cp_wait1();
        __syncthreads();

        unsigned sb = sbase + (unsigned)(it & 1) * (STG_W * 4);
        unsigned aHi = sb            + (unsigned)rb * (ROW_W*4) + aoff;
        unsigned aLo = sb + 2560*4   + (unsigned)rb * (ROW_W*4) + aoff;
        unsigned bHi = sb + 5120*4   + (unsigned)cb * (ROW_W*4) + boff;
        unsigned bLo = sb + 7680*4   + (unsigned)cb * (ROW_W*4) + boff;

#pragma unroll
        for (int kk = 0; kk < 2; kk++) {
            unsigned ah[2][4], al[2][4];
#pragma unroll
            for (int mi = 0; mi < 2; mi++) {
                ldsm_x4(ah[mi], aHi + mi * 1280 + kk * 32);
                ldsm_x4(al[mi], aLo + mi * 1280 + kk * 32);
            }
#pragma unroll
            for (int j = 0; j < 4; j++) {
                unsigned bh[4], bl[4];
                ldsm_x4(bh, bHi + j * 1280 + kk * 32);
                ldsm_x4(bl, bLo + j * 1280 + kk * 32);
#pragma unroll
                for (int p = 0; p < 2; p++) {
                    int nj = 2 * j + p;
#pragma unroll
                    for (int mi = 0; mi < 2; mi++) {
                        mma_bf16(acc[mi][nj], ah[mi], bh[2*p], bh[2*p+1]);
                        mma_bf16(acc[mi][nj], ah[mi], bl[2*p], bl[2*p+1]);
                        mma_bf16(acc[mi][nj], al[mi], bh[2*p], bh[2*p+1]);
                    }
                }
            }
        }
        __syncthreads();
    }

    // epilogue
#pragma unroll
    for (int mi = 0; mi < 2; mi++) {
#pragma unroll
        for (int nj = 0; nj < 8; nj++) {
            int m0 = bm + rb + mi * 16 + g;
            int m1 = m0 + 8;
            int n  = bn + cb + nj * 8 + 2 * t;
            float2 bv = *(const float2*)(bias + n);
            float2 r0 = make_float2(acc[mi][nj][0] + bv.x, acc[mi][nj][1] + bv.y);
            float2 r1 = make_float2(acc[mi][nj][2] + bv.x, acc[mi][nj][3] + bv.y);
            if (MODE == 1) {
                int h = n >> 6, d = n & 63;
                int b0i = m0 >> 11, s0 = m0 & (S_-1);
                int b1i = m1 >> 11, s1 = m1 & (S_-1);
                size_t a0 = ((size_t)(b0i * H_ + h) * S_ + s0) * D_ + d;
                size_t a1 = ((size_t)(b1i * H_ + h) * S_ + s1) * D_ + d;
                unsigned h0, l0, h1, l1;
                split_pack(r0.x, r0.y, h0, l0);
                split_pack(r1.x, r1.y, h1, l1);
                *(unsigned*)(Ch + a0) = h0; *(unsigned*)(Cl + a0) = l0;
                *(unsigned*)(Ch + a1) = h1; *(unsigned*)(Cl + a1) = l1;
            } else {
                *(float2*)(Cf + (size_t)m0 * E_ + n) = r0;
                *(float2*)(Cf + (size_t)m1 * E_ + n) = r1;
            }
        }
    }
}

// ---------------------------------------------------------------------------
// Causal flash attention on tensor cores (bf16x3) with ldmatrix frag loads.
// Block = 4 warps, 64 q-rows. Key tile = 64. Smem stride 36 words
// (36r mod 32 = 4r -> conflict-free LDSM phases).
// ---------------------------------------------------------------------------
__global__ __launch_bounds__(128) void attn_tc_kernel(
    const __nv_bfloat16* __restrict__ qh, const __nv_bfloat16* __restrict__ ql,
    const __nv_bfloat16* __restrict__ kh, const __nv_bfloat16* __restrict__ kl,
    const __nv_bfloat16* __restrict__ vth, const __nv_bfloat16* __restrict__ vtl,
    __nv_bfloat16* __restrict__ oh, __nv_bfloat16* __restrict__ ol)
{
    __shared__ __align__(16) unsigned Ks_hi[64][36];
    __shared__ __align__(16) unsigned Ks_lo[64][36];
    __shared__ __align__(16) unsigned Vt_hi[64][36];
    __shared__ __align__(16) unsigned Vt_lo[64][36];

    const int qt = (gridDim.x - 1) - blockIdx.x;   // heavy tiles first
    const int bh = blockIdx.y;
    const int b  = bh >> 4;
    const int h  = bh & 15;
    const int tid  = threadIdx.x;
    const int warp = tid >> 5;
    const int lane = tid & 31;
    const int g = lane >> 2;
    const int t = lane & 3;

    // ldmatrix per-lane offset (B operand pattern, stride 36 words)
    const int brow  = ((lane >> 4) * 8) + (lane & 7);
    const int bcolw = ((lane >> 3) & 1) * 4;
    const unsigned foff = (unsigned)(brow * 36 + bcolw) * 4;
    const unsigned ksh_a = s2u(Ks_hi) + foff;
    const unsigned ksl_a = s2u(Ks_lo) + foff;
    const unsigned vth_a = s2u(Vt_hi) + foff;
    const unsigned vtl_a = s2u(Vt_lo) + foff;

    const size_t qkbase = (size_t)bh * S_ * D_;
    const size_t vtbase = (size_t)bh * D_ * S_;
    const int r0 = qt * 64 + warp * 16 + g;   // global q row
    const int r1 = r0 + 8;

    // Q fragments (hi/lo), k = d in 4 chunks of 16
    unsigned qfh[4][4], qfl[4][4];
    {
        const unsigned* q0h = (const unsigned*)(qh + qkbase + (size_t)r0 * D_);
        const unsigned* q1h = (const unsigned*)(qh + qkbase + (size_t)r1 * D_);
        const unsigned* q0l = (const unsigned*)(ql + qkbase + (size_t)r0 * D_);
        const unsigned* q1l = (const unsigned*)(ql + qkbase + (size_t)r1 * D_);
#pragma unroll
        for (int kk = 0; kk < 4; kk++) {
            qfh[kk][0] = q0h[kk*8 + t];     qfh[kk][1] = q1h[kk*8 + t];
            qfh[kk][2] = q0h[kk*8 + t + 4]; qfh[kk][3] = q1h[kk*8 + t + 4];
            qfl[kk][0] = q0l[kk*8 + t];     qfl[kk][1] = q1l[kk*8 + t];
            qfl[kk][2] = q0l[kk*8 + t + 4]; qfl[kk][3] = q1l[kk*8 + t + 4];
        }
    }

    float o[8][4];
#pragma unroll
    for (int j = 0; j < 8; j++)
#pragma unroll
        for (int c = 0; c < 4; c++) o[j][c] = 0.f;
    float mrow[2] = {-1e30f, -1e30f};
    float lrow[2] = {0.f, 0.f};
    const float scale = 0.125f;

    for (int kt = 0; kt <= qt; kt++) {
        __syncthreads();
#pragma unroll
        for (int i = 0; i < 4; i++) {
            int fid = tid + i * 128;
            int row = fid >> 3;          // key index (K) / d index (Vt)
            int q8  = (fid & 7) * 8;     // bf16 col offset
            size_t gk = qkbase + (size_t)(kt * 64 + row) * D_ + q8;
            *(uint4*)&Ks_hi[row][(fid & 7) * 4] = *(const uint4*)(kh + gk);
            *(uint4*)&Ks_lo[row][(fid & 7) * 4] = *(const uint4*)(kl + gk);
            size_t gv = vtbase + (size_t)row * S_ + kt * 64 + q8;
            *(uint4*)&Vt_hi[row][(fid & 7) * 4] = *(const uint4*)(vth + gv);
            *(uint4*)&Vt_lo[row][(fid & 7) * 4] = *(const uint4*)(vtl + gv);
        }
        __syncthreads();

        // scores: m16 x 64 keys, contract over d=64
        float s[8][4];
#pragma unroll
        for (int j = 0; j < 8; j++)
#pragma unroll
            for (int c = 0; c < 4; c++) s[j][c] = 0.f;
#pragma unroll
        for (int kk = 0; kk < 4; kk++) {
#pragma unroll
            for (int j = 0; j < 4; j++) {
                unsigned bhf[4], blf[4];
                ldsm_x4(bhf, ksh_a + j * 2304 + kk * 32);
                ldsm_x4(blf, ksl_a + j * 2304 + kk * 32);
#pragma unroll
                for (int p = 0; p < 2; p++) {
                    int nj = 2 * j + p;
                    mma_bf16(s[nj], qfh[kk], bhf[2*p], bhf[2*p+1]);
                    mma_bf16(s[nj], qfh[kk], blf[2*p], blf[2*p+1]);
                    mma_bf16(s[nj], qfl[kk], bhf[2*p], bhf[2*p+1]);
                }
            }
        }

        // scale + causal mask (diagonal tile only)
#pragma unroll
        for (int nj = 0; nj < 8; nj++) {
            int c0 = kt * 64 + nj * 8 + 2 * t;
            s[nj][0] *= scale; s[nj][1] *= scale;
            s[nj][2] *= scale; s[nj][3] *= scale;
            if (kt == qt) {
                if (c0     > r0) s[nj][0] = -1e30f;
                if (c0 + 1 > r0) s[nj][1] = -1e30f;
                if (c0     > r1) s[nj][2] = -1e30f;
                if (c0 + 1 > r1) s[nj][3] = -1e30f;
            }
        }

        // online softmax (2 rows per thread; quad reduce over t lanes)
        float rm0 = -1e30f, rm1 = -1e30f;
#pragma unroll
        for (int nj = 0; nj < 8; nj++) {
            rm0 = fmaxf(rm0, fmaxf(s[nj][0], s[nj][1]));
            rm1 = fmaxf(rm1, fmaxf(s[nj][2], s[nj][3]));
        }
        rm0 = fmaxf(rm0, __shfl_xor_sync(0xffffffffu, rm0, 1));
        rm0 = fmaxf(rm0, __shfl_xor_sync(0xffffffffu, rm0, 2));
        rm1 = fmaxf(rm1, __shfl_xor_sync(0xffffffffu, rm1, 1));
        rm1 = fmaxf(rm1, __shfl_xor_sync(0xffffffffu, rm1, 2));
        float mn0 = fmaxf(mrow[0], rm0);
        float mn1 = fmaxf(mrow[1], rm1);
        float a0 = __expf(mrow[0] - mn0);
        float a1 = __expf(mrow[1] - mn1);
        float ps0 = 0.f, ps1 = 0.f;
#pragma unroll
        for (int nj = 0; nj < 8; nj++) {
            s[nj][0] = __expf(s[nj][0] - mn0);
            s[nj][1] = __expf(s[nj][1] - mn0);
            s[nj][2] = __expf(s[nj][2] - mn1);
            s[nj][3] = __expf(s[nj][3] - mn1);
            ps0 += s[nj][0] + s[nj][1];
            ps1 += s[nj][2] + s[nj][3];
        }
        ps0 += __shfl_xor_sync(0xffffffffu, ps0, 1);
        ps0 += __shfl_xor_sync(0xffffffffu, ps0, 2);
        ps1 += __shfl_xor_sync(0xffffffffu, ps1, 1);
        ps1 += __shfl_xor_sync(0xffffffffu, ps1, 2);
        lrow[0] = lrow[0] * a0 + ps0;
        lrow[1] = lrow[1] * a1 + ps1;
        mrow[0] = mn0; mrow[1] = mn1;
#pragma unroll
        for (int j = 0; j < 8; j++) {
            o[j][0] *= a0; o[j][1] *= a0;
            o[j][2] *= a1; o[j][3] *= a1;
        }

        // P·V: pack P into A-fragments (hi/lo), contract over 64 keys
#pragma unroll
        for (int kk = 0; kk < 4; kk++) {
            unsigned pa[4], pl[4];
            split_pack(s[2*kk  ][0], s[2*kk  ][1], pa[0], pl[0]);
            split_pack(s[2*kk  ][2], s[2*kk  ][3], pa[1], pl[1]);
            split_pack(s[2*kk+1][0], s[2*kk+1][1], pa[2], pl[2]);
            split_pack(s[2*kk+1][2], s[2*kk+1][3], pa[3], pl[3]);
#pragma unroll
            for (int j = 0; j < 4; j++) {
                unsigned bhf[4], blf[4];
                ldsm_x4(bhf, vth_a + j * 2304 + kk * 32);
                ldsm_x4(blf, vtl_a + j * 2304 + kk * 32);
#pragma unroll
                for (int p = 0; p < 2; p++) {
                    int jd = 2 * j + p;
                    mma_bf16(o[jd], pa, bhf[2*p], bhf[2*p+1]);
                    mma_bf16(o[jd], pa, blf[2*p], blf[2*p+1]);
                    mma_bf16(o[jd], pl, bhf[2*p], bhf[2*p+1]);
                }
            }
        }
    }

    // epilogue: normalize, split to bf16 hi/lo, write [B,S,E]
    float inv0 = 1.f / lrow[0];
    float inv1 = 1.f / lrow[1];
#pragma unroll
    for (int jd = 0; jd < 8; jd++) {
        int e = h * D_ + jd * 8 + 2 * t;
        size_t ad0 = ((size_t)b * S_ + r0) * E_ + e;
        size_t ad1 = ((size_t)b * S_ + r1) * E_ + e;
        unsigned h0, l0, h1, l1;
        split_pack(o[jd][0] * inv0, o[jd][1] * inv0, h0, l0);
        split_pack(o[jd][2] * inv1, o[jd][3] * inv1, h1, l1);
        *(unsigned*)(oh + ad0) = h0; *(unsigned*)(ol + ad0) = l0;
        *(unsigned*)(oh + ad1) = h1; *(unsigned*)(ol + ad1) = l1;
    }
}

// ---------------------------------------------------------------------------
extern "C" void kernel_launch(void* const* d_in, const int* in_sizes, int n_in,
                              void* d_out, int out_size)
{
    const float* Q  = (const float*)d_in[0];
    const float* K  = (const float*)d_in[1];
    const float* V  = (const float*)d_in[2];
    const float* Wq = (const float*)d_in[3];
    const float* bq = (const float*)d_in[4];
    const float* Wk = (const float*)d_in[5];
    const float* bk = (const float*)d_in[6];
    const float* Wv = (const float*)d_in[7];
    const float* bv = (const float*)d_in[8];
    const float* Wo = (const float*)d_in[9];
    const float* bo = (const float*)d_in[10];

    __nv_bfloat16 *xqh,*xql,*xkh,*xkl,*xvh,*xvl;
    __nv_bfloat16 *wqh,*wql,*wkh,*wkl,*wvh,*wvl,*woh,*wol;
    __nv_bfloat16 *qh,*ql,*kh,*kl,*vh,*vl,*vth,*vtl,*ah,*al;
    cudaGetSymbolAddress((void**)&xqh, g_xqh); cudaGetSymbolAddress((void**)&xql, g_xql);
    cudaGetSymbolAddress((void**)&xkh, g_xkh); cudaGetSymbolAddress((void**)&xkl, g_xkl);
    cudaGetSymbolAddress((void**)&xvh, g_xvh); cudaGetSymbolAddress((void**)&xvl, g_xvl);
    cudaGetSymbolAddress((void**)&wqh, g_wqh); cudaGetSymbolAddress((void**)&wql, g_wql);
    cudaGetSymbolAddress((void**)&wkh, g_wkh); cudaGetSymbolAddress((void**)&wkl, g_wkl);
    cudaGetSymbolAddress((void**)&wvh, g_wvh); cudaGetSymbolAddress((void**)&wvl, g_wvl);
    cudaGetSymbolAddress((void**)&woh, g_woh); cudaGetSymbolAddress((void**)&wol, g_wol);
    cudaGetSymbolAddress((void**)&qh, g_qh);   cudaGetSymbolAddress((void**)&ql, g_ql);
    cudaGetSymbolAddress((void**)&kh, g_kh);   cudaGetSymbolAddress((void**)&kl, g_kl);
    cudaGetSymbolAddress((void**)&vh, g_vh);   cudaGetSymbolAddress((void**)&vl, g_vl);
    cudaGetSymbolAddress((void**)&vth, g_vth); cudaGetSymbolAddress((void**)&vtl, g_vtl);
    cudaGetSymbolAddress((void**)&ah, g_ah);   cudaGetSymbolAddress((void**)&al, g_al);

    static bool attr_set = false;
    if (!attr_set) {
        cudaFuncSetAttribute(gemm_bf16_kernel<0>, cudaFuncAttributeMaxDynamicSharedMemorySize, 81920);
        cudaFuncSetAttribute(gemm_bf16_kernel<1>, cudaFuncAttributeMaxDynamicSharedMemorySize, 81920);
        attr_set = true;
    }

    const int n4x = NBSE / 4;   // 1M
    const int n4w = NEE / 4;    // 256K
    split_kernel<<<n4x/256, 256>>>((const float4*)Q,  (__nv_bfloat162*)xqh, (__nv_bfloat162*)xql, n4x);
    split_kernel<<<n4x/256, 256>>>((const float4*)K,  (__nv_bfloat162*)xkh, (__nv_bfloat162*)xkl, n4x);
    split_kernel<<<n4x/256, 256>>>((const float4*)V,  (__nv_bfloat162*)xvh, (__nv_bfloat162*)xvl, n4x);
    split_kernel<<<n4w/256, 256>>>((const float4*)Wq, (__nv_bfloat162*)wqh, (__nv_bfloat162*)wql, n4w);
    split_kernel<<<n4w/256, 256>>>((const float4*)Wk, (__nv_bfloat162*)wkh, (__nv_bfloat162*)wkl, n4w);
    split_kernel<<<n4w/256, 256>>>((const float4*)Wv, (__nv_bfloat162*)wvh, (__nv_bfloat162*)wvl, n4w);
    split_kernel<<<n4w/256, 256>>>((const float4*)Wo, (__nv_bfloat162*)woh, (__nv_bfloat162*)wol, n4w);

    dim3 gg(E_/128, M_/128);   // (8, 32)
    gemm_bf16_kernel<1><<<gg, 256, 81920>>>(xqh, xql, wqh, wql, bq, nullptr, qh, ql);
    gemm_bf16_kernel<1><<<gg, 256, 81920>>>(xkh, xkl, wkh, wkl, bk, nullptr, kh, kl);
    gemm_bf16_kernel<1><<<gg, 256, 81920>>>(xvh, xvl, wvh, wvl, bv, nullptr, vh, vl);

    transpose_v_kernel<<<dim3(S_/32, D_/32, B_*H_), dim3(32, 8)>>>(vh, vl, vth, vtl);

    attn_tc_kernel<<<dim3(S_/64, B_*H_), 128>>>(qh, ql, kh, kl, vth, vtl, ah, al);

    gemm_bf16_kernel<0><<<gg, 256, 81920>>>(ah, al, woh, wol, bo, (float*)d_out, nullptr, nullptr);
}